// round 5
// baseline (speedup 1.0000x reference)
#include <cuda_runtime.h>
#include <cstdint>
#include <cstddef>

// ---------------- problem constants ----------------
#define S_TOT   4096
#define DMODEL  1280
#define NHEAD   16
#define HD      80
#define NSEG    4
#define SEG_MAX 1024   // max segment length (scores stride)

// ---------------- GEMM tiling ----------------
#define BM 128
#define BN 128
#define BK 32
// As layout: [BM][BK+4]   (row stride 36 words)  -> conflict-free frag loads
// Bs NN:     [BK][BN+8]   (row stride 136 words)
// Bs NT:     [BN][BK+4]   (row stride 36 words)
#define AS_STRIDE (BK + 4)
#define BS_NN_STRIDE (BN + 8)
#define BS_NT_STRIDE (BK + 4)
#define BS_WORDS (BN * (BK + 4))   // 4608 >= BK*(BN+8)=4352

// ---------------- scratch (__device__ globals; no allocation) ----------------
__device__ float g_q[(size_t)NHEAD * S_TOT * HD];
__device__ float g_k[(size_t)NHEAD * S_TOT * HD];
__device__ float g_v[(size_t)NHEAD * S_TOT * HD];
__device__ float g_scores[(size_t)NHEAD * NSEG * SEG_MAX * SEG_MAX];  // 268 MB
__device__ float g_attn[(size_t)S_TOT * DMODEL];

// ---------------- helpers ----------------
__device__ __forceinline__ uint32_t f2tf(float x) {
    uint32_t r;
    asm("cvt.rna.tf32.f32 %0, %1;" : "=r"(r) : "f"(x));
    return r;
}

__device__ __forceinline__ void mma_tf32(float c[4], const uint32_t a[4], const uint32_t b[2]) {
    asm volatile(
        "mma.sync.aligned.m16n8k8.row.col.f32.tf32.tf32.f32 "
        "{%0,%1,%2,%3},{%4,%5,%6,%7},{%8,%9},{%0,%1,%2,%3};\n"
        : "+f"(c[0]), "+f"(c[1]), "+f"(c[2]), "+f"(c[3])
        : "r"(a[0]), "r"(a[1]), "r"(a[2]), "r"(a[3]),
          "r"(b[0]), "r"(b[1]));
}

// Generic tf32 block-GEMM mainloop.
//   A: (mA x K) row-major, lda = row stride
//   BT == false (NN): B is (K x nB) row-major  -> C = A @ B
//   BT == true  (NT): B is (nB x K) row-major  -> C = A @ B^T
// Computes the 128x128 tile at (m0, n0) into acc[4][4][4] (per-warp 64x32).
// 256 threads = 8 warps arranged 2(m) x 4(n).
template <bool BT>
__device__ __forceinline__ void gemm_mainloop(
    const float* __restrict__ A, int lda, int mA,
    const float* __restrict__ B, int ldb, int nB,
    int K, int m0, int n0, float acc[4][4][4])
{
    __shared__ uint32_t As[BM * AS_STRIDE];
    __shared__ uint32_t Bs[BS_WORDS];

    const int tid  = threadIdx.x;
    const int lane = tid & 31;
    const int warp = tid >> 5;
    const int wm   = (warp >> 2) * 64;  // 0 or 64
    const int wn   = (warp & 3) * 32;   // 0,32,64,96
    const int g    = lane >> 2;         // 0..7
    const int tg   = lane & 3;          // 0..3

    #pragma unroll
    for (int i = 0; i < 4; i++)
        #pragma unroll
        for (int j = 0; j < 4; j++)
            #pragma unroll
            for (int r = 0; r < 4; r++) acc[i][j][r] = 0.f;

    for (int k0 = 0; k0 < K; k0 += BK) {
        // ---- load A tile (BM x BK), coalesced along k ----
        {
            const int mrow = tid >> 5;   // 0..7
            const int kcol = lane;       // 0..31
            #pragma unroll
            for (int mm = mrow; mm < BM; mm += 8) {
                const int gm = m0 + mm;
                const int gk = k0 + kcol;
                float v = (gm < mA && gk < K) ? A[(size_t)gm * lda + gk] : 0.f;
                As[mm * AS_STRIDE + kcol] = f2tf(v);
            }
        }
        // ---- load B tile ----
        if constexpr (BT) {
            // B (nB x K): stage as Bs[n][k]
            const int nrow = tid >> 5;
            const int kcol = lane;
            #pragma unroll
            for (int nn = nrow; nn < BN; nn += 8) {
                const int gn = n0 + nn;
                const int gk = k0 + kcol;
                float v = (gn < nB && gk < K) ? B[(size_t)gn * ldb + gk] : 0.f;
                Bs[nn * BS_NT_STRIDE + kcol] = f2tf(v);
            }
        } else {
            // B (K x nB): stage as Bs[k][n]
            const int krow = tid >> 5;   // 0..7
            #pragma unroll
            for (int kk = krow; kk < BK; kk += 8) {
                const int gk = k0 + kk;
                #pragma unroll
                for (int j = 0; j < 4; j++) {
                    const int nn = j * 32 + lane;
                    const int gn = n0 + nn;
                    float v = (gk < K && gn < nB) ? B[(size_t)gk * ldb + gn] : 0.f;
                    Bs[kk * BS_NN_STRIDE + nn] = f2tf(v);
                }
            }
        }
        __syncthreads();

        // ---- compute: 4 k-steps of m16n8k8 ----
        #pragma unroll
        for (int ks = 0; ks < BK; ks += 8) {
            uint32_t af[4][4];
            uint32_t bf[4][2];
            #pragma unroll
            for (int mi = 0; mi < 4; mi++) {
                const int mb = wm + mi * 16;
                af[mi][0] = As[(mb + g    ) * AS_STRIDE + ks + tg];
                af[mi][1] = As[(mb + g + 8) * AS_STRIDE + ks + tg];
                af[mi][2] = As[(mb + g    ) * AS_STRIDE + ks + tg + 4];
                af[mi][3] = As[(mb + g + 8) * AS_STRIDE + ks + tg + 4];
            }
            #pragma unroll
            for (int ni = 0; ni < 4; ni++) {
                const int nb = wn + ni * 8;
                if constexpr (BT) {
                    bf[ni][0] = Bs[(nb + g) * BS_NT_STRIDE + ks + tg];
                    bf[ni][1] = Bs[(nb + g) * BS_NT_STRIDE + ks + tg + 4];
                } else {
                    bf[ni][0] = Bs[(ks + tg    ) * BS_NN_STRIDE + nb + g];
                    bf[ni][1] = Bs[(ks + tg + 4) * BS_NN_STRIDE + nb + g];
                }
            }
            #pragma unroll
            for (int mi = 0; mi < 4; mi++)
                #pragma unroll
                for (int ni = 0; ni < 4; ni++)
                    mma_tf32(acc[mi][ni], af[mi], bf[ni]);
        }
        __syncthreads();
    }
}

// Epilogue index helpers (c-fragment layout of m16n8k8):
//   row = m0 + wm + mi*16 + g + ((r>>1)*8), col = n0 + wn + ni*8 + tg*2 + (r&1)
#define EPILOGUE_VARS                                   \
    const int lane = threadIdx.x & 31;                  \
    const int warp = threadIdx.x >> 5;                  \
    const int wm = (warp >> 2) * 64;                    \
    const int wn = (warp & 3) * 32;                     \
    const int g = lane >> 2;                            \
    const int tg = lane & 3;

// ---------------- kernel 1: QKV GEMM, scatter into per-head q/k/v ----------------
__global__ __launch_bounds__(256)
void qkv_kernel(const float* __restrict__ A, const float* __restrict__ B,
                const float* __restrict__ bias)
{
    float acc[4][4][4];
    const int m0 = blockIdx.x * BM;
    const int n0 = blockIdx.y * BN;
    gemm_mainloop<false>(A, DMODEL, S_TOT, B, 3 * DMODEL, 3 * DMODEL, DMODEL, m0, n0, acc);

    EPILOGUE_VARS
    #pragma unroll
    for (int mi = 0; mi < 4; mi++)
        #pragma unroll
        for (int ni = 0; ni < 4; ni++)
            #pragma unroll
            for (int r = 0; r < 4; r++) {
                const int row = m0 + wm + mi * 16 + g + ((r >> 1) << 3);
                const int col = n0 + wn + ni * 8 + tg * 2 + (r & 1);
                float v = acc[mi][ni][r] + bias[col];
                const int which = col / DMODEL;
                const int rem = col - which * DMODEL;
                const int h = rem / HD;
                const int d = rem - h * HD;
                float* dst = (which == 0) ? g_q : ((which == 1) ? g_k : g_v);
                dst[((size_t)h * S_TOT + row) * HD + d] = v;
            }
}

// ---------------- kernel 2: RoPE on q,k (+ pre-scale q by 1/sqrt(hd)) ----------------
__global__ void rope_kernel(const float* __restrict__ rot)
{
    const int idx = blockIdx.x * blockDim.x + threadIdx.x;
    const int total = 2 * NHEAD * S_TOT * (HD / 2);
    if (idx >= total) return;
    const int half = HD / 2;                      // 40
    const int dd = idx % half;
    const int s  = (idx / half) % S_TOT;
    const int h  = (idx / (half * S_TOT)) % NHEAD;
    const int which = idx / (half * S_TOT * NHEAD);

    const float f = rot[s * half + dd];
    const float c = cosf(f);
    const float sn = sinf(f);

    float* buf = which ? g_k : g_q;
    const size_t base = ((size_t)h * S_TOT + s) * HD;
    const float x1 = buf[base + dd];
    const float x2 = buf[base + dd + half];
    float o1 = x1 * c - x2 * sn;
    float o2 = x1 * sn + x2 * c;
    if (which == 0) {   // q: fold in 1/sqrt(80) attention scale
        const float qs = 0.11180339887498949f;
        o1 *= qs; o2 *= qs;
    }
    buf[base + dd] = o1;
    buf[base + dd + half] = o2;
}

// ---------------- kernel 3: scores = Qseg @ Kseg^T (batched over h x seg) ----------------
__global__ __launch_bounds__(256)
void scores_kernel(const int* __restrict__ cu)
{
    const int z = blockIdx.z;         // 0..63
    const int h = z >> 2;
    const int seg = z & 3;
    const int s0 = cu[seg];
    const int L = cu[seg + 1] - s0;
    const int m0 = blockIdx.x * BM;
    const int n0 = blockIdx.y * BN;
    if (m0 >= L || n0 >= L) return;

    const float* Qp = g_q + ((size_t)h * S_TOT + s0) * HD;
    const float* Kp = g_k + ((size_t)h * S_TOT + s0) * HD;

    float acc[4][4][4];
    gemm_mainloop<true>(Qp, HD, L, Kp, HD, L, HD, m0, n0, acc);

    EPILOGUE_VARS
    float* Sout = g_scores + (size_t)z * SEG_MAX * SEG_MAX;
    #pragma unroll
    for (int mi = 0; mi < 4; mi++)
        #pragma unroll
        for (int ni = 0; ni < 4; ni++)
            #pragma unroll
            for (int r = 0; r < 4; r++) {
                const int row = m0 + wm + mi * 16 + g + ((r >> 1) << 3);
                const int col = n0 + wn + ni * 8 + tg * 2 + (r & 1);
                if (row < L && col < L)
                    Sout[(size_t)row * SEG_MAX + col] = acc[mi][ni][r];
            }
}

// ---------------- kernel 4: row softmax over scores ----------------
__global__ void softmax_kernel(const int* __restrict__ cu)
{
    const int z = blockIdx.x >> 10;       // batch 0..63
    const int r = blockIdx.x & 1023;      // row within segment
    const int seg = z & 3;
    const int s0 = cu[seg];
    const int L = cu[seg + 1] - s0;
    if (r >= L) return;

    float* row = g_scores + (size_t)z * SEG_MAX * SEG_MAX + (size_t)r * SEG_MAX;
    const int tid = threadIdx.x;          // 128 threads

    float v[8];
    float mx = -3.4e38f;
    #pragma unroll
    for (int i = 0; i < 8; i++) {
        const int c = tid + i * 128;
        v[i] = (c < L) ? row[c] : -3.4e38f;
        mx = fmaxf(mx, v[i]);
    }
    #pragma unroll
    for (int o = 16; o > 0; o >>= 1) mx = fmaxf(mx, __shfl_xor_sync(0xffffffffu, mx, o));
    __shared__ float red_mx[4];
    if ((tid & 31) == 0) red_mx[tid >> 5] = mx;
    __syncthreads();
    mx = fmaxf(fmaxf(red_mx[0], red_mx[1]), fmaxf(red_mx[2], red_mx[3]));

    float sum = 0.f;
    #pragma unroll
    for (int i = 0; i < 8; i++) {
        const int c = tid + i * 128;
        float e = (c < L) ? expf(v[i] - mx) : 0.f;
        v[i] = e;
        sum += e;
    }
    #pragma unroll
    for (int o = 16; o > 0; o >>= 1) sum += __shfl_xor_sync(0xffffffffu, sum, o);
    __shared__ float red_sum[4];
    if ((tid & 31) == 0) red_sum[tid >> 5] = sum;
    __syncthreads();
    sum = red_sum[0] + red_sum[1] + red_sum[2] + red_sum[3];
    const float inv = 1.f / sum;

    #pragma unroll
    for (int i = 0; i < 8; i++) {
        const int c = tid + i * 128;
        if (c < L) row[c] = v[i] * inv;
    }
}

// ---------------- kernel 5: attn_out = P @ Vseg (batched) ----------------
__global__ __launch_bounds__(256)
void pv_kernel(const int* __restrict__ cu)
{
    const int z = blockIdx.z;
    const int h = z >> 2;
    const int seg = z & 3;
    const int s0 = cu[seg];
    const int L = cu[seg + 1] - s0;
    const int m0 = blockIdx.x * BM;
    if (m0 >= L) return;

    const float* P  = g_scores + (size_t)z * SEG_MAX * SEG_MAX;
    const float* Vp = g_v + ((size_t)h * S_TOT + s0) * HD;

    float acc[4][4][4];
    gemm_mainloop<false>(P, SEG_MAX, L, Vp, HD, HD, L, m0, 0, acc);

    EPILOGUE_VARS
    #pragma unroll
    for (int mi = 0; mi < 4; mi++)
        #pragma unroll
        for (int ni = 0; ni < 4; ni++)
            #pragma unroll
            for (int r = 0; r < 4; r++) {
                const int row = m0 + wm + mi * 16 + g + ((r >> 1) << 3);
                const int col = wn + ni * 8 + tg * 2 + (r & 1);
                if (row < L && col < HD)
                    g_attn[(size_t)(s0 + row) * DMODEL + h * HD + col] = acc[mi][ni][r];
            }
}

// ---------------- kernel 6: out = attn @ w_proj + b_proj ----------------
__global__ __launch_bounds__(256)
void proj_kernel(const float* __restrict__ B, const float* __restrict__ bias,
                 float* __restrict__ out)
{
    float acc[4][4][4];
    const int m0 = blockIdx.x * BM;
    const int n0 = blockIdx.y * BN;
    gemm_mainloop<false>(g_attn, DMODEL, S_TOT, B, DMODEL, DMODEL, DMODEL, m0, n0, acc);

    EPILOGUE_VARS
    #pragma unroll
    for (int mi = 0; mi < 4; mi++)
        #pragma unroll
        for (int ni = 0; ni < 4; ni++)
            #pragma unroll
            for (int r = 0; r < 4; r++) {
                const int row = m0 + wm + mi * 16 + g + ((r >> 1) << 3);
                const int col = n0 + wn + ni * 8 + tg * 2 + (r & 1);
                out[(size_t)row * DMODEL + col] = acc[mi][ni][r] + bias[col];
            }
}

// ---------------- launch ----------------
extern "C" void kernel_launch(void* const* d_in, const int* in_sizes, int n_in,
                              void* d_out, int out_size)
{
    (void)in_sizes; (void)n_in; (void)out_size;
    const float* hidden = (const float*)d_in[0];
    const int*   cu     = (const int*)  d_in[1];
    const float* rot    = (const float*)d_in[2];
    const float* w_qkv  = (const float*)d_in[3];
    const float* b_qkv  = (const float*)d_in[4];
    const float* w_proj = (const float*)d_in[5];
    const float* b_proj = (const float*)d_in[6];
    float* out = (float*)d_out;

    // 1. QKV GEMM: (4096 x 1280) @ (1280 x 3840) -> scattered q/k/v (H,S,hd)
    qkv_kernel<<<dim3(S_TOT / BM, 3 * DMODEL / BN), 256>>>(hidden, w_qkv, b_qkv);

    // 2. RoPE on q,k (q pre-scaled by 1/sqrt(hd))
    {
        const int total = 2 * NHEAD * S_TOT * (HD / 2);
        rope_kernel<<<(total + 255) / 256, 256>>>(rot);
    }

    // 3. scores = Q @ K^T per (head, segment)
    scores_kernel<<<dim3(SEG_MAX / BM, SEG_MAX / BN, NHEAD * NSEG), 256>>>(cu);

    // 4. softmax per row
    softmax_kernel<<<NHEAD * NSEG * SEG_MAX, 128>>>(cu);

    // 5. attn = P @ V per (head, segment) -> (S, 1280)
    pv_kernel<<<dim3(SEG_MAX / BM, 1, NHEAD * NSEG), 256>>>(cu);

    // 6. out = attn @ w_proj + b_proj
    proj_kernel<<<dim3(S_TOT / BM, DMODEL / BN), 256>>>(w_proj, b_proj, out);
}

// round 7
// speedup vs baseline: 2.0179x; 2.0179x over previous
#include <cuda_runtime.h>
#include <cstdint>
#include <cstddef>

// ---------------- problem constants ----------------
#define S_TOT   4096
#define DMODEL  1280
#define NHEAD   16
#define HD      80
#define NSEG    4
#define SEG_MAX 1024   // max segment length (scores stride)

// ---------------- GEMM tiling ----------------
#define BM 128
#define BN 128
#define BK 32
// As layout: [BM][BK+4]   (row stride 36 words)  -> conflict-free frag loads
// Bs NN:     [BK][BN+8]   (row stride 136 words)
// Bs NT:     [BN][BK+4]   (row stride 36 words)
#define AS_STRIDE (BK + 4)
#define BS_NN_STRIDE (BN + 8)
#define BS_NT_STRIDE (BK + 4)
#define BS_WORDS (BN * (BK + 4))   // 4608 >= BK*(BN+8)=4352

// ---------------- scratch (__device__ globals; no allocation) ----------------
__device__ float g_q[(size_t)NHEAD * S_TOT * HD];
__device__ float g_k[(size_t)NHEAD * S_TOT * HD];
__device__ float g_v[(size_t)NHEAD * S_TOT * HD];
__device__ float g_scores[(size_t)NHEAD * NSEG * SEG_MAX * SEG_MAX];  // 268 MB
__device__ float g_attn[(size_t)S_TOT * DMODEL];

// ---------------- helpers ----------------
__device__ __forceinline__ uint32_t f2tf(float x) {
    uint32_t r;
    asm("cvt.rna.tf32.f32 %0, %1;" : "=r"(r) : "f"(x));
    return r;
}

__device__ __forceinline__ void mma_tf32(float c[4], const uint32_t a[4], const uint32_t b[2]) {
    asm volatile(
        "mma.sync.aligned.m16n8k8.row.col.f32.tf32.tf32.f32 "
        "{%0,%1,%2,%3},{%4,%5,%6,%7},{%8,%9},{%0,%1,%2,%3};\n"
        : "+f"(c[0]), "+f"(c[1]), "+f"(c[2]), "+f"(c[3])
        : "r"(a[0]), "r"(a[1]), "r"(a[2]), "r"(a[3]),
          "r"(b[0]), "r"(b[1]));
}

// 16-byte cp.async with zero-fill when predicate is false.
// (src-size = 0 -> all 16 bytes of the smem destination are zero-filled)
__device__ __forceinline__ void cp16(float* smem_dst, const float* gsrc, bool pred) {
    uint32_t d = (uint32_t)__cvta_generic_to_shared(smem_dst);
    int sz = pred ? 16 : 0;
    asm volatile("cp.async.cg.shared.global [%0], [%1], 16, %2;\n"
                 :: "r"(d), "l"(gsrc), "r"(sz) : "memory");
}
__device__ __forceinline__ void cp_commit() {
    asm volatile("cp.async.commit_group;\n" ::: "memory");
}
template <int N>
__device__ __forceinline__ void cp_wait() {
    asm volatile("cp.async.wait_group %0;\n" :: "n"(N) : "memory");
}

// Stage one (BM x BK) A tile and one B tile into smem via cp.async.
// All global leading dimensions in this problem are multiples of 4 floats, so
// every 16B granule is all-valid or all-invalid (zero-filled).
template <bool BT>
__device__ __forceinline__ void load_tiles(
    float* __restrict__ As, float* __restrict__ Bs,
    const float* __restrict__ A, int lda, int mA,
    const float* __restrict__ B, int ldb, int nB,
    int K, int m0, int n0, int k0, int tid)
{
    // ---- A tile: 128 rows x 8 granules (of 4 floats) ----
    {
        const int gran = tid & 7;        // 0..7
        const int row0 = tid >> 3;       // 0..31
        const int gk = k0 + gran * 4;
        const bool kok = gk < K;
        #pragma unroll
        for (int mm = row0; mm < BM; mm += 32) {
            const int gm = m0 + mm;
            const bool p = kok && (gm < mA);
            const float* src = p ? (A + (size_t)gm * lda + gk) : A;
            cp16(&As[mm * AS_STRIDE + gran * 4], src, p);
        }
    }
    if constexpr (BT) {
        // B (nB x K), stage as Bs[n][k]: 128 rows x 8 granules
        const int gran = tid & 7;
        const int row0 = tid >> 3;
        const int gk = k0 + gran * 4;
        const bool kok = gk < K;
        #pragma unroll
        for (int nn = row0; nn < BN; nn += 32) {
            const int gn = n0 + nn;
            const bool p = kok && (gn < nB);
            const float* src = p ? (B + (size_t)gn * ldb + gk) : B;
            cp16(&Bs[nn * BS_NT_STRIDE + gran * 4], src, p);
        }
    } else {
        // B (K x nB), stage as Bs[k][n]: 32 rows x 32 granules
        const int gran = tid & 31;       // 0..31 -> n offset gran*4
        const int row0 = tid >> 5;       // 0..7
        const int gn = n0 + gran * 4;
        const bool nok = gn < nB;
        #pragma unroll
        for (int kk = row0; kk < BK; kk += 8) {
            const int gk = k0 + kk;
            const bool p = nok && (gk < K);
            const float* src = p ? (B + (size_t)gk * ldb + gn) : B;
            cp16(&Bs[kk * BS_NN_STRIDE + gran * 4], src, p);
        }
    }
}

// Generic tf32 block-GEMM mainloop, 2-stage cp.async pipeline.
//   A: (mA x K) row-major, lda = row stride
//   BT == false (NN): B is (K x nB) row-major  -> C = A @ B
//   BT == true  (NT): B is (nB x K) row-major  -> C = A @ B^T
// Computes the 128x128 tile at (m0, n0) into acc[4][4][4] (per-warp 64x32).
// 256 threads = 8 warps arranged 2(m) x 4(n).
template <bool BT>
__device__ __forceinline__ void gemm_mainloop(
    const float* __restrict__ A, int lda, int mA,
    const float* __restrict__ B, int ldb, int nB,
    int K, int m0, int n0, float acc[4][4][4])
{
    __shared__ float As[2][BM * AS_STRIDE];
    __shared__ float Bs[2][BS_WORDS];

    const int tid  = threadIdx.x;
    const int lane = tid & 31;
    const int warp = tid >> 5;
    const int wm   = (warp >> 2) * 64;  // 0 or 64
    const int wn   = (warp & 3) * 32;   // 0,32,64,96
    const int g    = lane >> 2;         // 0..7
    const int tg   = lane & 3;          // 0..3

    #pragma unroll
    for (int i = 0; i < 4; i++)
        #pragma unroll
        for (int j = 0; j < 4; j++)
            #pragma unroll
            for (int r = 0; r < 4; r++) acc[i][j][r] = 0.f;

    const int nk = (K + BK - 1) / BK;

    // prologue: stage 0
    load_tiles<BT>(As[0], Bs[0], A, lda, mA, B, ldb, nB, K, m0, n0, 0, tid);
    cp_commit();

    for (int it = 0; it < nk; ++it) {
        // issue next stage (or an empty group to keep the wait count uniform)
        if (it + 1 < nk) {
            load_tiles<BT>(As[(it + 1) & 1], Bs[(it + 1) & 1],
                           A, lda, mA, B, ldb, nB, K, m0, n0, (it + 1) * BK, tid);
        }
        cp_commit();
        cp_wait<1>();          // current stage's group has landed
        __syncthreads();

        const float* cAs = As[it & 1];
        const float* cBs = Bs[it & 1];

        // ---- compute: 4 k-steps of m16n8k8 ----
        #pragma unroll
        for (int ks = 0; ks < BK; ks += 8) {
            uint32_t af[4][4];
            uint32_t bf[4][2];
            #pragma unroll
            for (int mi = 0; mi < 4; mi++) {
                const int mb = wm + mi * 16;
                af[mi][0] = f2tf(cAs[(mb + g    ) * AS_STRIDE + ks + tg]);
                af[mi][1] = f2tf(cAs[(mb + g + 8) * AS_STRIDE + ks + tg]);
                af[mi][2] = f2tf(cAs[(mb + g    ) * AS_STRIDE + ks + tg + 4]);
                af[mi][3] = f2tf(cAs[(mb + g + 8) * AS_STRIDE + ks + tg + 4]);
            }
            #pragma unroll
            for (int ni = 0; ni < 4; ni++) {
                const int nb = wn + ni * 8;
                if constexpr (BT) {
                    bf[ni][0] = f2tf(cBs[(nb + g) * BS_NT_STRIDE + ks + tg]);
                    bf[ni][1] = f2tf(cBs[(nb + g) * BS_NT_STRIDE + ks + tg + 4]);
                } else {
                    bf[ni][0] = f2tf(cBs[(ks + tg    ) * BS_NN_STRIDE + nb + g]);
                    bf[ni][1] = f2tf(cBs[(ks + tg + 4) * BS_NN_STRIDE + nb + g]);
                }
            }
            #pragma unroll
            for (int mi = 0; mi < 4; mi++)
                #pragma unroll
                for (int ni = 0; ni < 4; ni++)
                    mma_tf32(acc[mi][ni], af[mi], bf[ni]);
        }
        __syncthreads();   // all warps done with this buffer before it is re-filled
    }
}

// Epilogue index helpers (c-fragment layout of m16n8k8):
//   row = m0 + wm + mi*16 + g + ((r>>1)*8), col = n0 + wn + ni*8 + tg*2 + (r&1)
#define EPILOGUE_VARS                                   \
    const int lane = threadIdx.x & 31;                  \
    const int warp = threadIdx.x >> 5;                  \
    const int wm = (warp >> 2) * 64;                    \
    const int wn = (warp & 3) * 32;                     \
    const int g = lane >> 2;                            \
    const int tg = lane & 3;

// ---------------- kernel 1: QKV GEMM, scatter into per-head q/k/v ----------------
__global__ __launch_bounds__(256)
void qkv_kernel(const float* __restrict__ A, const float* __restrict__ B,
                const float* __restrict__ bias)
{
    float acc[4][4][4];
    const int m0 = blockIdx.x * BM;
    const int n0 = blockIdx.y * BN;
    gemm_mainloop<false>(A, DMODEL, S_TOT, B, 3 * DMODEL, 3 * DMODEL, DMODEL, m0, n0, acc);

    EPILOGUE_VARS
    #pragma unroll
    for (int mi = 0; mi < 4; mi++)
        #pragma unroll
        for (int ni = 0; ni < 4; ni++)
            #pragma unroll
            for (int r = 0; r < 4; r++) {
                const int row = m0 + wm + mi * 16 + g + ((r >> 1) << 3);
                const int col = n0 + wn + ni * 8 + tg * 2 + (r & 1);
                float v = acc[mi][ni][r] + bias[col];
                const int which = col / DMODEL;
                const int rem = col - which * DMODEL;
                const int h = rem / HD;
                const int d = rem - h * HD;
                float* dst = (which == 0) ? g_q : ((which == 1) ? g_k : g_v);
                dst[((size_t)h * S_TOT + row) * HD + d] = v;
            }
}

// ---------------- kernel 2: RoPE on q,k (+ pre-scale q by 1/sqrt(hd)) ----------------
__global__ void rope_kernel(const float* __restrict__ rot)
{
    const int idx = blockIdx.x * blockDim.x + threadIdx.x;
    const int total = 2 * NHEAD * S_TOT * (HD / 2);
    if (idx >= total) return;
    const int half = HD / 2;                      // 40
    const int dd = idx % half;
    const int s  = (idx / half) % S_TOT;
    const int h  = (idx / (half * S_TOT)) % NHEAD;
    const int which = idx / (half * S_TOT * NHEAD);

    const float f = rot[s * half + dd];
    const float c = cosf(f);
    const float sn = sinf(f);

    float* buf = which ? g_k : g_q;
    const size_t base = ((size_t)h * S_TOT + s) * HD;
    const float x1 = buf[base + dd];
    const float x2 = buf[base + dd + half];
    float o1 = x1 * c - x2 * sn;
    float o2 = x1 * sn + x2 * c;
    if (which == 0) {   // q: fold in 1/sqrt(80) attention scale
        const float qs = 0.11180339887498949f;
        o1 *= qs; o2 *= qs;
    }
    buf[base + dd] = o1;
    buf[base + dd + half] = o2;
}

// ---------------- kernel 3: scores = Qseg @ Kseg^T (batched over h x seg) ----------------
__global__ __launch_bounds__(256)
void scores_kernel(const int* __restrict__ cu)
{
    const int z = blockIdx.z;         // 0..63
    const int h = z >> 2;
    const int seg = z & 3;
    const int s0 = cu[seg];
    const int L = cu[seg + 1] - s0;
    const int m0 = blockIdx.x * BM;
    const int n0 = blockIdx.y * BN;
    if (m0 >= L || n0 >= L) return;

    const float* Qp = g_q + ((size_t)h * S_TOT + s0) * HD;
    const float* Kp = g_k + ((size_t)h * S_TOT + s0) * HD;

    float acc[4][4][4];
    gemm_mainloop<true>(Qp, HD, L, Kp, HD, L, HD, m0, n0, acc);

    EPILOGUE_VARS
    float* Sout = g_scores + (size_t)z * SEG_MAX * SEG_MAX;
    #pragma unroll
    for (int mi = 0; mi < 4; mi++)
        #pragma unroll
        for (int ni = 0; ni < 4; ni++)
            #pragma unroll
            for (int r = 0; r < 4; r++) {
                const int row = m0 + wm + mi * 16 + g + ((r >> 1) << 3);
                const int col = n0 + wn + ni * 8 + tg * 2 + (r & 1);
                if (row < L && col < L)
                    Sout[(size_t)row * SEG_MAX + col] = acc[mi][ni][r];
            }
}

// ---------------- kernel 4: row softmax over scores ----------------
__global__ void softmax_kernel(const int* __restrict__ cu)
{
    const int z = blockIdx.x >> 10;       // batch 0..63
    const int r = blockIdx.x & 1023;      // row within segment
    const int seg = z & 3;
    const int s0 = cu[seg];
    const int L = cu[seg + 1] - s0;
    if (r >= L) return;

    float* row = g_scores + (size_t)z * SEG_MAX * SEG_MAX + (size_t)r * SEG_MAX;
    const int tid = threadIdx.x;          // 128 threads

    float v[8];
    float mx = -3.4e38f;
    #pragma unroll
    for (int i = 0; i < 8; i++) {
        const int c = tid + i * 128;
        v[i] = (c < L) ? row[c] : -3.4e38f;
        mx = fmaxf(mx, v[i]);
    }
    #pragma unroll
    for (int o = 16; o > 0; o >>= 1) mx = fmaxf(mx, __shfl_xor_sync(0xffffffffu, mx, o));
    __shared__ float red_mx[4];
    if ((tid & 31) == 0) red_mx[tid >> 5] = mx;
    __syncthreads();
    mx = fmaxf(fmaxf(red_mx[0], red_mx[1]), fmaxf(red_mx[2], red_mx[3]));

    float sum = 0.f;
    #pragma unroll
    for (int i = 0; i < 8; i++) {
        const int c = tid + i * 128;
        float e = (c < L) ? expf(v[i] - mx) : 0.f;
        v[i] = e;
        sum += e;
    }
    #pragma unroll
    for (int o = 16; o > 0; o >>= 1) sum += __shfl_xor_sync(0xffffffffu, sum, o);
    __shared__ float red_sum[4];
    if ((tid & 31) == 0) red_sum[tid >> 5] = sum;
    __syncthreads();
    sum = red_sum[0] + red_sum[1] + red_sum[2] + red_sum[3];
    const float inv = 1.f / sum;

    #pragma unroll
    for (int i = 0; i < 8; i++) {
        const int c = tid + i * 128;
        if (c < L) row[c] = v[i] * inv;
    }
}

// ---------------- kernel 5: attn_out = P @ Vseg (batched) ----------------
__global__ __launch_bounds__(256)
void pv_kernel(const int* __restrict__ cu)
{
    const int z = blockIdx.z;
    const int h = z >> 2;
    const int seg = z & 3;
    const int s0 = cu[seg];
    const int L = cu[seg + 1] - s0;
    const int m0 = blockIdx.x * BM;
    if (m0 >= L) return;

    const float* P  = g_scores + (size_t)z * SEG_MAX * SEG_MAX;
    const float* Vp = g_v + ((size_t)h * S_TOT + s0) * HD;

    float acc[4][4][4];
    gemm_mainloop<false>(P, SEG_MAX, L, Vp, HD, HD, L, m0, 0, acc);

    EPILOGUE_VARS
    #pragma unroll
    for (int mi = 0; mi < 4; mi++)
        #pragma unroll
        for (int ni = 0; ni < 4; ni++)
            #pragma unroll
            for (int r = 0; r < 4; r++) {
                const int row = m0 + wm + mi * 16 + g + ((r >> 1) << 3);
                const int col = wn + ni * 8 + tg * 2 + (r & 1);
                if (row < L && col < HD)
                    g_attn[(size_t)(s0 + row) * DMODEL + h * HD + col] = acc[mi][ni][r];
            }
}

// ---------------- kernel 6: out = attn @ w_proj + b_proj ----------------
__global__ __launch_bounds__(256)
void proj_kernel(const float* __restrict__ B, const float* __restrict__ bias,
                 float* __restrict__ out)
{
    float acc[4][4][4];
    const int m0 = blockIdx.x * BM;
    const int n0 = blockIdx.y * BN;
    gemm_mainloop<false>(g_attn, DMODEL, S_TOT, B, DMODEL, DMODEL, DMODEL, m0, n0, acc);

    EPILOGUE_VARS
    #pragma unroll
    for (int mi = 0; mi < 4; mi++)
        #pragma unroll
        for (int ni = 0; ni < 4; ni++)
            #pragma unroll
            for (int r = 0; r < 4; r++) {
                const int row = m0 + wm + mi * 16 + g + ((r >> 1) << 3);
                const int col = n0 + wn + ni * 8 + tg * 2 + (r & 1);
                out[(size_t)row * DMODEL + col] = acc[mi][ni][r] + bias[col];
            }
}

// ---------------- launch ----------------
extern "C" void kernel_launch(void* const* d_in, const int* in_sizes, int n_in,
                              void* d_out, int out_size)
{
    (void)in_sizes; (void)n_in; (void)out_size;
    const float* hidden = (const float*)d_in[0];
    const int*   cu     = (const int*)  d_in[1];
    const float* rot    = (const float*)d_in[2];
    const float* w_qkv  = (const float*)d_in[3];
    const float* b_qkv  = (const float*)d_in[4];
    const float* w_proj = (const float*)d_in[5];
    const float* b_proj = (const float*)d_in[6];
    float* out = (float*)d_out;

    // 1. QKV GEMM: (4096 x 1280) @ (1280 x 3840) -> scattered q/k/v (H,S,hd)
    qkv_kernel<<<dim3(S_TOT / BM, 3 * DMODEL / BN), 256>>>(hidden, w_qkv, b_qkv);

    // 2. RoPE on q,k (q pre-scaled by 1/sqrt(hd))
    {
        const int total = 2 * NHEAD * S_TOT * (HD / 2);
        rope_kernel<<<(total + 255) / 256, 256>>>(rot);
    }

    // 3. scores = Q @ K^T per (head, segment)
    scores_kernel<<<dim3(SEG_MAX / BM, SEG_MAX / BN, NHEAD * NSEG), 256>>>(cu);

    // 4. softmax per row
    softmax_kernel<<<NHEAD * NSEG * SEG_MAX, 128>>>(cu);

    // 5. attn = P @ V per (head, segment) -> (S, 1280)
    pv_kernel<<<dim3(SEG_MAX / BM, 1, NHEAD * NSEG), 256>>>(cu);

    // 6. out = attn @ w_proj + b_proj
    proj_kernel<<<dim3(S_TOT / BM, DMODEL / BN), 256>>>(w_proj, b_proj, out);
}